// round 11
// baseline (speedup 1.0000x reference)
#include <cuda_runtime.h>
#include <cuda_fp16.h>
#include <cstdint>

#define IN_F   512
#define OUT_F  512
#define BATCH  16384
#define NSTEP  72            // 8 silu chunks + 64 spline chunks, all fp16
#define TILE   16384         // 128 rows x 128B
#define RB_BYTES (NSTEP * TILE)           // 1.125 MB per rowblock
#define DYN    (6 * TILE + 1024)          // 3 A-buf + 3 B-buf

__device__ char g_A[(size_t)128 * RB_BYTES];        // 144 MB (L2-transient)
__device__ char g_W[(size_t)NSTEP * OUT_F * 128];   // 4.7 MB packed fp16 weights
__device__ unsigned g_sync[132];                    // [0..127] per-rb A count, [128] W count

// ---------------- helpers ----------------
static __device__ __forceinline__ uint32_t smem_u32(const void* p) {
    uint32_t a;
    asm("{ .reg .u64 t; cvta.to.shared.u64 t, %1; cvt.u32.u64 %0, t; }" : "=r"(a) : "l"(p));
    return a;
}
static __device__ __forceinline__ void cp16(uint32_t dst, const void* src) {
    asm volatile("cp.async.cg.shared.global [%0], [%1], 16;" :: "r"(dst), "l"(src) : "memory");
}
#define CP_COMMIT() asm volatile("cp.async.commit_group;" ::: "memory")
#define CP_WAIT1()  asm volatile("cp.async.wait_group 1;" ::: "memory")

static __device__ __forceinline__ void ldsm4(uint32_t* r, uint32_t a) {
    asm volatile("ldmatrix.sync.aligned.m8n8.x4.shared.b16 {%0,%1,%2,%3}, [%4];"
                 : "=r"(r[0]), "=r"(r[1]), "=r"(r[2]), "=r"(r[3]) : "r"(a));
}
static __device__ __forceinline__ void mma_f16(float* d, const uint32_t* a, const uint32_t* b) {
    asm volatile("mma.sync.aligned.m16n8k16.row.col.f32.f16.f16.f32 "
                 "{%0,%1,%2,%3}, {%4,%5,%6,%7}, {%8,%9}, {%0,%1,%2,%3};"
                 : "+f"(d[0]), "+f"(d[1]), "+f"(d[2]), "+f"(d[3])
                 : "r"(a[0]), "r"(a[1]), "r"(a[2]), "r"(a[3]), "r"(b[0]), "r"(b[1]));
}
static __device__ __forceinline__ uint32_t pk2h(float lo, float hi) {   // low half = lo
    uint32_t r; asm("cvt.rn.f16x2.f32 %0, %1, %2;" : "=r"(r) : "f"(hi), "f"(lo)); return r;
}
static __device__ __forceinline__ uint32_t swz(uint32_t byteoff) {
    return byteoff ^ ((byteoff >> 3) & 0x70);
}
static __device__ __forceinline__ float silu_fast(float x) {
    float th;
    asm("tanh.approx.f32 %0, %1;" : "=f"(th) : "f"(0.5f * x));
    float hx = 0.5f * x;
    return fmaf(hx, th, hx);
}
// cardinal cubic B-spline N3(s), support (0,4), branchless
static __device__ __forceinline__ float n3(float s) {
    float m = fmaxf(fminf(s, 4.0f - s), 0.0f);
    float d = fmaxf(m - 1.0f, 0.0f);
    return (m * m * m - 4.0f * d * d * d) * (1.0f / 6.0f);
}

// ---------------- counter reset (graph-replay safe) ----------------
__global__ void zero_sync() { g_sync[threadIdx.x] = 0u; }

// ---------------- fused kernel ----------------
__global__ __launch_bounds__(256, 2)
void kan_fused(const float* __restrict__ bw, const float* __restrict__ sw,
               const float* __restrict__ sc, const float* __restrict__ x,
               const float* __restrict__ grid, float* __restrict__ out) {
    extern __shared__ char dynraw[];
    const int tid = threadIdx.x;
    const int bid = blockIdx.x;
    const int rb = bid >> 2, nidx = bid & 3;
    const int m0 = rb * 128, n0 = nidx * 128;

    // ---- Phase 0: W pack, CTAs bid<128 (each 1/128 slice; 72*4096 units total) ----
    if (bid < 128) {
#pragma unroll 1
        for (int it = 0; it < 9; it++) {
            int u = bid * 2304 + it * 256 + tid;
            int st = u >> 12, r = u & 4095;
            int n = r >> 3, sg = r & 7;
            float4 a, b;
            if (st < 8) {
                const float4* p = (const float4*)(bw + n * IN_F + st * 64 + sg * 8);
                a = p[0]; b = p[1];
            } else {
                int k = (st - 8) * 8 + sg;
                float scv = sc[n * IN_F + k];
                const float4* p = (const float4*)(sw + ((size_t)n * IN_F + k) * 8);
                a = p[0]; b = p[1];
                a.x *= scv; a.y *= scv; a.z *= scv; a.w *= scv;
                b.x *= scv; b.y *= scv; b.z *= scv; b.w *= scv;
            }
            *(uint4*)(g_W + (size_t)st * 65536 + swz((unsigned)(n * 128 + sg * 16))) =
                make_uint4(pk2h(a.x, a.y), pk2h(a.z, a.w), pk2h(b.x, b.y), pk2h(b.z, b.w));
        }
        __threadfence();
        __syncthreads();
        if (tid == 0) atomicAdd(&g_sync[128], 1u);
    }

    // ---- Phase 1: generate this CTA's A share (18 of rb's 72 tiles) ----
    const float g0 = grid[0];
    const float invh = 1.0f / (grid[1] - grid[0]);
    char* Arb = g_A + (size_t)rb * RB_BYTES;
#pragma unroll 1
    for (int tt = 0; tt < 18; tt++) {
        int t = nidx * 18 + tt;
        char* tile = Arb + t * TILE;
        if (t < 8) {
            // silu chunk t: thread -> (row, 8-feat group)
#pragma unroll
            for (int it = 0; it < 4; it++) {
                int v = it * 256 + tid;
                int row = v >> 3, kg = v & 7;
                const float4* xp = (const float4*)(x + (size_t)(m0 + row) * IN_F + t * 64 + kg * 8);
                float4 xa = xp[0], xb = xp[1];
                *(uint4*)(tile + swz((unsigned)(row * 128 + kg * 16))) = make_uint4(
                    pk2h(silu_fast(xa.x), silu_fast(xa.y)),
                    pk2h(silu_fast(xa.z), silu_fast(xa.w)),
                    pk2h(silu_fast(xb.x), silu_fast(xb.y)),
                    pk2h(silu_fast(xb.z), silu_fast(xb.w)));
            }
        } else {
            // spline chunk c: thread -> (row, one feature: 8 bases = 16B)
            int c = t - 8;
#pragma unroll
            for (int it = 0; it < 4; it++) {
                int v = it * 256 + tid;
                int row = v >> 3, ff = v & 7;
                float xv = x[(size_t)(m0 + row) * IN_F + c * 8 + ff];
                float uu = (xv - g0) * invh;
                *(uint4*)(tile + swz((unsigned)(row * 128 + ff * 16))) = make_uint4(
                    pk2h(n3(uu),        n3(uu - 1.0f)),
                    pk2h(n3(uu - 2.0f), n3(uu - 3.0f)),
                    pk2h(n3(uu - 4.0f), n3(uu - 5.0f)),
                    pk2h(n3(uu - 6.0f), n3(uu - 7.0f)));
            }
        }
    }
    __threadfence();
    __syncthreads();
    if (tid == 0) atomicAdd(&g_sync[rb], 1u);

    // ---- Phase 2: wait for W (all 128 packers) + this rb's 4 producers ----
    if (tid == 0) {
        while (*(volatile unsigned*)&g_sync[128] < 128u) __nanosleep(128);
        while (*(volatile unsigned*)&g_sync[rb] < 4u) __nanosleep(64);
        __threadfence();
    }
    __syncthreads();

    // ---- Phase 3: streaming fp16 GEMM (unchanged from R8-10) ----
    uint32_t sbase = (smem_u32(dynraw) + 1023u) & ~1023u;
    const uint32_t A0 = sbase,            A1 = sbase + TILE,     A2 = sbase + 2 * TILE;
    const uint32_t B0 = sbase + 3 * TILE, B1 = sbase + 4 * TILE, B2 = sbase + 5 * TILE;

    const int l = tid & 31, wid = tid >> 5;
    const int wm = wid & 1, wn = wid >> 1;     // warp tile 64 x 32

    uint32_t offA[4], swzA[4];
#pragma unroll
    for (int mt = 0; mt < 4; mt++) {
        int rA = wm * 64 + mt * 16 + (l & 7) + (((l >> 3) & 1) << 3);
        offA[mt] = (uint32_t)(rA * 128);
        swzA[mt] = (uint32_t)((rA & 7) << 4);
    }
    const uint32_t colAsub = (uint32_t)((l >> 4) << 4);
    uint32_t offB[2], swzB[2];
#pragma unroll
    for (int nt2 = 0; nt2 < 2; nt2++) {
        int rB = wn * 32 + nt2 * 16 + (l & 7) + ((l >> 4) << 3);
        offB[nt2] = (uint32_t)(rB * 128);
        swzB[nt2] = (uint32_t)((rB & 7) << 4);
    }
    const uint32_t colBsub = (uint32_t)(((l >> 3) & 1) << 4);

    const char* Aglob = Arb;
    const char* Bglob = g_W + (size_t)n0 * 128;

    float acc[4][4][4];
#pragma unroll
    for (int a = 0; a < 4; a++)
#pragma unroll
        for (int b = 0; b < 4; b++)
#pragma unroll
            for (int c = 0; c < 4; c++) acc[a][b][c] = 0.0f;

    const uint32_t t16 = (uint32_t)(tid * 16);

    auto step = [&](int s, uint32_t Ab, uint32_t Bb, uint32_t Ad2, uint32_t Bd2) {
        CP_WAIT1();
        __syncthreads();

        const bool pf = (s + 2 < NSTEP);
        const char* As2 = Aglob + (size_t)(s + 2) * TILE;
        const char* Bs2 = Bglob + (size_t)(s + 2) * 65536;

#pragma unroll
        for (int ks = 0; ks < 4; ks++) {
            uint32_t af[4][4];
#pragma unroll
            for (int mt = 0; mt < 4; mt++)
                ldsm4(af[mt], Ab + offA[mt] + ((ks * 32 + colAsub) ^ swzA[mt]));
            uint32_t bf[4][2];
#pragma unroll
            for (int nt2 = 0; nt2 < 2; nt2++) {
                uint32_t r[4];
                ldsm4(r, Bb + offB[nt2] + ((ks * 32 + colBsub) ^ swzB[nt2]));
                bf[2 * nt2][0] = r[0]; bf[2 * nt2][1] = r[1];
                bf[2 * nt2 + 1][0] = r[2]; bf[2 * nt2 + 1][1] = r[3];
            }
#pragma unroll
            for (int mt = 0; mt < 4; mt++)
#pragma unroll
                for (int nt = 0; nt < 4; nt++)
                    mma_f16(acc[mt][nt], af[mt], bf[nt]);

            if (ks == 0 && pf) {
#pragma unroll
                for (int it = 0; it < 4; it++)
                    cp16(Ad2 + t16 + it * 4096, As2 + t16 + it * 4096);
            }
            if (ks == 1 && pf) {
#pragma unroll
                for (int it = 0; it < 4; it++)
                    cp16(Bd2 + t16 + it * 4096, Bs2 + t16 + it * 4096);
            }
        }
        CP_COMMIT();
    };

    // prologue: load steps 0, 1
    {
        const char* As = Aglob;
        const char* Bs = Bglob;
#pragma unroll
        for (int it = 0; it < 4; it++) {
            cp16(A0 + t16 + it * 4096, As + t16 + it * 4096);
            cp16(B0 + t16 + it * 4096, Bs + t16 + it * 4096);
        }
        CP_COMMIT();
        As += TILE; Bs += 65536;
#pragma unroll
        for (int it = 0; it < 4; it++) {
            cp16(A1 + t16 + it * 4096, As + t16 + it * 4096);
            cp16(B1 + t16 + it * 4096, Bs + t16 + it * 4096);
        }
        CP_COMMIT();
    }

    for (int s = 0; s < NSTEP; s += 3) {
        step(s,     A0, B0, A2, B2);
        step(s + 1, A1, B1, A0, B0);
        step(s + 2, A2, B2, A1, B1);
    }

    // ---- epilogue ----
#pragma unroll
    for (int mt = 0; mt < 4; mt++) {
#pragma unroll
        for (int nt = 0; nt < 4; nt++) {
            int m = m0 + wm * 64 + mt * 16 + (l >> 2);
            int n = n0 + wn * 32 + nt * 8 + (l & 3) * 2;
            *(float2*)(out + (size_t)m * OUT_F + n) = make_float2(acc[mt][nt][0], acc[mt][nt][1]);
            *(float2*)(out + (size_t)(m + 8) * OUT_F + n) = make_float2(acc[mt][nt][2], acc[mt][nt][3]);
        }
    }
}

extern "C" void kernel_launch(void* const* d_in, const int* in_sizes, int n_in,
                              void* d_out, int out_size) {
    const float* x    = (const float*)d_in[0];
    const float* bw   = (const float*)d_in[1];
    const float* sw   = (const float*)d_in[2];
    const float* sc   = (const float*)d_in[3];
    const float* grid = (const float*)d_in[4];
    float*       out  = (float*)d_out;

    cudaFuncSetAttribute(kan_fused, cudaFuncAttributeMaxDynamicSharedMemorySize, DYN);

    zero_sync<<<1, 132>>>();
    kan_fused<<<512, 256, DYN>>>(bw, sw, sc, x, grid, out);
}

// round 13
// speedup vs baseline: 1.4634x; 1.4634x over previous
#include <cuda_runtime.h>
#include <cuda_fp16.h>
#include <cstdint>

#define IN_F   512
#define OUT_F  512
#define BATCH  16384
#define BM     128
#define BN     128
#define NSTEP  72            // 8 silu chunks + 64 spline chunks, all fp16 single-pass
#define TILE   16384         // 128 rows x 128B (64 fp16 K-slots)
#define RB_BYTES (NSTEP * TILE)           // 1.125 MB per rowblock
#define DYN    (6 * TILE + 1024)          // 3 A-buf + 3 B-buf = 97 KB

#define PACK_BLOCKS   (NSTEP * OUT_F * 64 / 256)   // 9216
#define SPLINE_BLOCKS (BATCH * IN_F / 256)         // 32768

__device__ char g_A[(size_t)128 * RB_BYTES];        // 144 MB augmented activations
__device__ char g_W[(size_t)NSTEP * OUT_F * 128];   // 4.7 MB packed fp16 weights

// ---------------- helpers ----------------
static __device__ __forceinline__ uint32_t smem_u32(const void* p) {
    uint32_t a;
    asm("{ .reg .u64 t; cvta.to.shared.u64 t, %1; cvt.u32.u64 %0, t; }" : "=r"(a) : "l"(p));
    return a;
}
static __device__ __forceinline__ void cp16(uint32_t dst, const void* src) {
    asm volatile("cp.async.cg.shared.global [%0], [%1], 16;" :: "r"(dst), "l"(src) : "memory");
}
#define CP_COMMIT() asm volatile("cp.async.commit_group;" ::: "memory")
#define CP_WAIT1()  asm volatile("cp.async.wait_group 1;" ::: "memory")

static __device__ __forceinline__ void ldsm4(uint32_t* r, uint32_t a) {
    asm volatile("ldmatrix.sync.aligned.m8n8.x4.shared.b16 {%0,%1,%2,%3}, [%4];"
                 : "=r"(r[0]), "=r"(r[1]), "=r"(r[2]), "=r"(r[3]) : "r"(a));
}
static __device__ __forceinline__ void mma_f16(float* d, const uint32_t* a, const uint32_t* b) {
    asm volatile("mma.sync.aligned.m16n8k16.row.col.f32.f16.f16.f32 "
                 "{%0,%1,%2,%3}, {%4,%5,%6,%7}, {%8,%9}, {%0,%1,%2,%3};"
                 : "+f"(d[0]), "+f"(d[1]), "+f"(d[2]), "+f"(d[3])
                 : "r"(a[0]), "r"(a[1]), "r"(a[2]), "r"(a[3]), "r"(b[0]), "r"(b[1]));
}
static __device__ __forceinline__ uint32_t pk2h(float lo, float hi) {   // low half = lo
    uint32_t r; asm("cvt.rn.f16x2.f32 %0, %1, %2;" : "=r"(r) : "f"(hi), "f"(lo)); return r;
}
static __device__ __forceinline__ uint32_t swz(uint32_t byteoff) {
    return byteoff ^ ((byteoff >> 3) & 0x70);
}
// silu via single-MUFU tanh approx: silu(x) = 0.5x * (1 + tanh(x/2))
static __device__ __forceinline__ float silu_fast(float x) {
    float th;
    asm("tanh.approx.f32 %0, %1;" : "=f"(th) : "f"(0.5f * x));
    float hx = 0.5f * x;
    return fmaf(hx, th, hx);
}
// cardinal cubic B-spline N3(s), support (0,4), branchless
static __device__ __forceinline__ float n3(float s) {
    float m = fmaxf(fminf(s, 4.0f - s), 0.0f);
    float d = fmaxf(m - 1.0f, 0.0f);
    return (m * m * m - 4.0f * d * d * d) * (1.0f / 6.0f);
}

// ---------------- fused prep (single pass over x) ----------------
// blocks [0, PACK)   : pack weights (fp16, pre-swizzled)
// blocks [PACK, ...) : spline + silu, store-coalesced, x read exactly once
__global__ __launch_bounds__(256)
void prep(const float* __restrict__ bw, const float* __restrict__ sw,
          const float* __restrict__ sc, const float* __restrict__ x,
          const float* __restrict__ grid) {
    if (blockIdx.x < PACK_BLOCKS) {
        int idx = blockIdx.x * 256 + threadIdx.x;
        int st = idx >> 15, r = idx & 32767;
        int n = r >> 6, slot = r & 63;
        float w;
        if (st < 8) {
            w = bw[n * IN_F + st * 64 + slot];
        } else {
            int c = st - 8;
            int k = c * 8 + (slot >> 3), j = slot & 7;
            w = sw[((size_t)n * IN_F + k) * 8 + j] * sc[n * IN_F + k];
        }
        *(__half*)(g_W + (size_t)st * 65536 + swz((unsigned)(n * 128 + slot * 2))) =
            __float2half_rn(w);
        return;
    }

    // warp -> (chunk c, 4 consecutive rows); lane -> (row, one feature)
    int idx = (blockIdx.x - PACK_BLOCKS) * 256 + threadIdx.x;   // 16384 * 512
    int w = idx >> 5, l = idx & 31;
    int c = w & 63, rg = w >> 6;                  // chunk, row-group
    int m = rg * 4 + (l >> 3);                    // global row
    int ff = l & 7;                               // feature within chunk
    int rb = m >> 7, row = m & 127;

    const float g0 = grid[0];
    const float invh = 1.0f / (grid[1] - grid[0]);

    char* Arb = g_A + (size_t)rb * RB_BYTES;
    float xv = x[(size_t)m * IN_F + c * 8 + ff];

    // spline: 8 bases = 16B, warp store = 4 x 128B contiguous swizzled rows
    float uu = (xv - g0) * invh;
    uint4 v = make_uint4(pk2h(n3(uu),        n3(uu - 1.0f)),
                         pk2h(n3(uu - 2.0f), n3(uu - 3.0f)),
                         pk2h(n3(uu - 4.0f), n3(uu - 5.0f)),
                         pk2h(n3(uu - 6.0f), n3(uu - 7.0f)));
    *(uint4*)(Arb + (8 + c) * TILE + swz((unsigned)(row * 128 + ff * 16))) = v;

    // silu: one fp16 into silu chunk c>>3, slot (c&7)*8+ff.
    // swizzle xor is constant across the 16B group (ff*2 < 16 never reaches bit 7),
    // so the 8 lanes of a row store 16 contiguous bytes.
    unsigned sbase = swz((unsigned)(row * 128 + (c & 7) * 16));
    *(__half*)(Arb + (c >> 3) * TILE + sbase + ff * 2) = __float2half_rn(silu_fast(xv));
}

// ---------------- main kernel: uniform streaming fp16 GEMM (R10, unchanged) ----------------
__global__ __launch_bounds__(256, 2)
void kan_mma(float* __restrict__ out) {
    extern __shared__ char dynraw[];
    const int tid = threadIdx.x;
    const int rb = blockIdx.y;
    const int m0 = rb * BM;
    const int n0 = blockIdx.x * BN;

    uint32_t sbase = (smem_u32(dynraw) + 1023u) & ~1023u;
    const uint32_t A0 = sbase,          A1 = sbase + TILE,     A2 = sbase + 2 * TILE;
    const uint32_t B0 = sbase + 3*TILE, B1 = sbase + 4 * TILE, B2 = sbase + 5 * TILE;

    const int l = tid & 31, wid = tid >> 5;
    const int wm = wid & 1, wn = wid >> 1;     // warp tile 64 x 32

    uint32_t offA[4], swzA[4];
#pragma unroll
    for (int mt = 0; mt < 4; mt++) {
        int rA = wm * 64 + mt * 16 + (l & 7) + (((l >> 3) & 1) << 3);
        offA[mt] = (uint32_t)(rA * 128);
        swzA[mt] = (uint32_t)((rA & 7) << 4);
    }
    const uint32_t colAsub = (uint32_t)((l >> 4) << 4);
    uint32_t offB[2], swzB[2];
#pragma unroll
    for (int nt2 = 0; nt2 < 2; nt2++) {
        int rB = wn * 32 + nt2 * 16 + (l & 7) + ((l >> 4) << 3);
        offB[nt2] = (uint32_t)(rB * 128);
        swzB[nt2] = (uint32_t)((rB & 7) << 4);
    }
    const uint32_t colBsub = (uint32_t)(((l >> 3) & 1) << 4);

    const char* Aglob = g_A + (size_t)rb * RB_BYTES;
    const char* Bglob = g_W + (size_t)n0 * 128;

    float acc[4][4][4];
#pragma unroll
    for (int a = 0; a < 4; a++)
#pragma unroll
        for (int b = 0; b < 4; b++)
#pragma unroll
            for (int c = 0; c < 4; c++) acc[a][b][c] = 0.0f;

    const uint32_t t16 = (uint32_t)(tid * 16);

    auto step = [&](int s, uint32_t Ab, uint32_t Bb, uint32_t Ad2, uint32_t Bd2) {
        CP_WAIT1();
        __syncthreads();

        const bool pf = (s + 2 < NSTEP);
        const char* As2 = Aglob + (size_t)(s + 2) * TILE;
        const char* Bs2 = Bglob + (size_t)(s + 2) * 65536;

#pragma unroll
        for (int ks = 0; ks < 4; ks++) {
            uint32_t af[4][4];
#pragma unroll
            for (int mt = 0; mt < 4; mt++)
                ldsm4(af[mt], Ab + offA[mt] + ((ks * 32 + colAsub) ^ swzA[mt]));
            uint32_t bf[4][2];
#pragma unroll
            for (int nt2 = 0; nt2 < 2; nt2++) {
                uint32_t r[4];
                ldsm4(r, Bb + offB[nt2] + ((ks * 32 + colBsub) ^ swzB[nt2]));
                bf[2 * nt2][0] = r[0]; bf[2 * nt2][1] = r[1];
                bf[2 * nt2 + 1][0] = r[2]; bf[2 * nt2 + 1][1] = r[3];
            }
#pragma unroll
            for (int mt = 0; mt < 4; mt++)
#pragma unroll
                for (int nt = 0; nt < 4; nt++)
                    mma_f16(acc[mt][nt], af[mt], bf[nt]);

            if (ks == 0 && pf) {
#pragma unroll
                for (int it = 0; it < 4; it++)
                    cp16(Ad2 + t16 + it * 4096, As2 + t16 + it * 4096);
            }
            if (ks == 1 && pf) {
#pragma unroll
                for (int it = 0; it < 4; it++)
                    cp16(Bd2 + t16 + it * 4096, Bs2 + t16 + it * 4096);
            }
        }
        CP_COMMIT();
    };

    // prologue: load steps 0, 1
    {
        const char* As = Aglob;
        const char* Bs = Bglob;
#pragma unroll
        for (int it = 0; it < 4; it++) {
            cp16(A0 + t16 + it * 4096, As + t16 + it * 4096);
            cp16(B0 + t16 + it * 4096, Bs + t16 + it * 4096);
        }
        CP_COMMIT();
        As += TILE; Bs += 65536;
#pragma unroll
        for (int it = 0; it < 4; it++) {
            cp16(A1 + t16 + it * 4096, As + t16 + it * 4096);
            cp16(B1 + t16 + it * 4096, Bs + t16 + it * 4096);
        }
        CP_COMMIT();
    }

    for (int s = 0; s < NSTEP; s += 3) {
        step(s,     A0, B0, A2, B2);
        step(s + 1, A1, B1, A0, B0);
        step(s + 2, A2, B2, A1, B1);
    }

    // ---- epilogue ----
#pragma unroll
    for (int mt = 0; mt < 4; mt++) {
#pragma unroll
        for (int nt = 0; nt < 4; nt++) {
            int m = m0 + wm * 64 + mt * 16 + (l >> 2);
            int n = n0 + wn * 32 + nt * 8 + (l & 3) * 2;
            *(float2*)(out + (size_t)m * OUT_F + n) = make_float2(acc[mt][nt][0], acc[mt][nt][1]);
            *(float2*)(out + (size_t)(m + 8) * OUT_F + n) = make_float2(acc[mt][nt][2], acc[mt][nt][3]);
        }
    }
}

extern "C" void kernel_launch(void* const* d_in, const int* in_sizes, int n_in,
                              void* d_out, int out_size) {
    const float* x    = (const float*)d_in[0];
    const float* bw   = (const float*)d_in[1];
    const float* sw   = (const float*)d_in[2];
    const float* sc   = (const float*)d_in[3];
    const float* grid = (const float*)d_in[4];
    float*       out  = (float*)d_out;

    cudaFuncSetAttribute(kan_mma, cudaFuncAttributeMaxDynamicSharedMemorySize, DYN);

    prep<<<PACK_BLOCKS + SPLINE_BLOCKS, 256>>>(bw, sw, sc, x, grid);

    dim3 g(OUT_F / BN, BATCH / BM);   // (4, 128) = 512 CTAs
    kan_mma<<<g, 256, DYN>>>(out);
}